// round 15
// baseline (speedup 1.0000x reference)
#include <cuda_runtime.h>
#include <math.h>

#define DIMC 512
#define NHEADS 8
#define HD 64
#define FSZ 56
#define NTOK 3136
#define KTOK 784
#define BATCH 4
#define ATT_SCALE 0.125f
#define LN_EPS 1e-5f
#define POSW 111

// ---------------- scratch ----------------
__device__ float g_bias[NTOK * KTOK];
__device__ float g_q[BATCH * NHEADS * NTOK * HD];
__device__ float g_xr[BATCH * KTOK * DIMC];
__device__ float g_k[BATCH * NHEADS * KTOK * HD];
__device__ float g_v[BATCH * NHEADS * KTOK * HD];
__device__ float g_ao[BATCH * NTOK * DIMC];

// ---------------- tf32 helpers ----------------
__device__ __forceinline__ unsigned f2tf(float f) {
    unsigned u; asm("cvt.rna.tf32.f32 %0, %1;" : "=r"(u) : "f"(f)); return u;
}
__device__ __forceinline__ uint4 tf4(float4 v) {
    uint4 t; t.x = f2tf(v.x); t.y = f2tf(v.y); t.z = f2tf(v.z); t.w = f2tf(v.w); return t;
}
#define MMA8(C, A, B)                                                          \
    asm volatile(                                                              \
        "mma.sync.aligned.m16n8k8.row.col.f32.tf32.tf32.f32 "                  \
        "{%0,%1,%2,%3},{%4,%5,%6,%7},{%8,%9},{%0,%1,%2,%3};"                   \
        : "+f"((C)[0]), "+f"((C)[1]), "+f"((C)[2]), "+f"((C)[3])               \
        : "r"((A)[0]), "r"((A)[1]), "r"((A)[2]), "r"((A)[3]),                  \
          "r"((B)[0]), "r"((B)[1]))

#define APAD 136
#define BPAD 72

// Fragment compute for one 16-k tile: As[16][APAD] (k,m), Bs[16][BPAD] (k,n).
__device__ __forceinline__ void mma_tile16(const unsigned* __restrict__ As,
                                           const unsigned* __restrict__ Bs,
                                           float c[2][4][4], int wm, int wn,
                                           int g, int tig) {
#pragma unroll
    for (int kk = 0; kk < 16; kk += 8) {
        unsigned a[2][4], bf[4][2];
#pragma unroll
        for (int mt = 0; mt < 2; mt++) {
            int mr = wm * 32 + mt * 16 + g;
            a[mt][0] = As[(kk + tig) * APAD + mr];
            a[mt][1] = As[(kk + tig) * APAD + mr + 8];
            a[mt][2] = As[(kk + tig + 4) * APAD + mr];
            a[mt][3] = As[(kk + tig + 4) * APAD + mr + 8];
        }
#pragma unroll
        for (int nt = 0; nt < 4; nt++) {
            int nc = wn * 32 + nt * 8 + g;
            bf[nt][0] = Bs[(kk + tig) * BPAD + nc];
            bf[nt][1] = Bs[(kk + tig + 4) * BPAD + nc];
        }
#pragma unroll
        for (int mt = 0; mt < 2; mt++)
#pragma unroll
            for (int nt = 0; nt < 4; nt++) MMA8(c[mt][nt], a[mt], bf[nt]);
    }
}

// ---------------- bias precompute (2 elems/thread) ----------------
__global__ void bias_kernel(const float* __restrict__ pos, const int* __restrict__ rel) {
    int i = blockIdx.x * 256 + threadIdx.x;
    if (i >= NTOK * KTOK / 2) return;
    int e = 2 * i;
    int n = e / KTOK, m = e % KTOK;
    int4 r = *(const int4*)&rel[((long long)n * NTOK + m) * 2];
    float2 o;
    o.x = pos[r.x * POSW + r.y];
    o.y = pos[r.z * POSW + r.w];
    *(float2*)&g_bias[e] = o;
}

// ---------------- GEMM Q (tf32): A[m][k]=x[b][k][m], B=Wq. M=3136,N=512,K=512 ----------------
__global__ __launch_bounds__(256) void gemm_q(const float* __restrict__ x,
                                              const float* __restrict__ Wq) {
    __shared__ unsigned As[16 * APAD];
    __shared__ unsigned Bs[16 * BPAD];
    int b = blockIdx.z, m0 = blockIdx.y * 128, n0 = blockIdx.x * 64;
    int tid = threadIdx.x, lane = tid & 31, warp = tid >> 5;
    int g = lane >> 2, tig = lane & 3;
    int wm = warp >> 1, wn = warp & 1;
    const float* xb = x + (size_t)b * DIMC * NTOK;
    float c[2][4][4] = {};
    for (int k0 = 0; k0 < DIMC; k0 += 16) {
#pragma unroll
        for (int e = tid; e < 512; e += 256) {
            int kr = e >> 5, c4 = (e & 31) * 4;
            float4 v = make_float4(0.f, 0.f, 0.f, 0.f);
            if (m0 + c4 < NTOK)
                v = *(const float4*)&xb[(size_t)(k0 + kr) * NTOK + m0 + c4];
            *(uint4*)&As[kr * APAD + c4] = tf4(v);
        }
        {
            int kr = tid >> 4, c4 = (tid & 15) * 4;
            float4 v = *(const float4*)&Wq[(size_t)(k0 + kr) * DIMC + n0 + c4];
            *(uint4*)&Bs[kr * BPAD + c4] = tf4(v);
        }
        __syncthreads();
        mma_tile16(As, Bs, c, wm, wn, g, tig);
        __syncthreads();
    }
#pragma unroll
    for (int mt = 0; mt < 2; mt++) {
        int r1 = m0 + wm * 32 + mt * 16 + g, r2 = r1 + 8;
#pragma unroll
        for (int nt = 0; nt < 4; nt++) {
            int n = n0 + wn * 32 + nt * 8 + tig * 2;
            int h = n >> 6, d = n & 63;
            if (r1 < NTOK)
                *(float2*)&g_q[(((size_t)b * NHEADS + h) * NTOK + r1) * HD + d] =
                    make_float2(c[mt][nt][0], c[mt][nt][1]);
            if (r2 < NTOK)
                *(float2*)&g_q[(((size_t)b * NHEADS + h) * NTOK + r2) * HD + d] =
                    make_float2(c[mt][nt][2], c[mt][nt][3]);
        }
    }
}

// ---------------- GEMM conv (tf32): im2col, M=784, N=512, K=2048 ----------------
__global__ __launch_bounds__(256) void gemm_conv(const float* __restrict__ x,
                                                 const float* __restrict__ Wsr,
                                                 const float* __restrict__ b_sr) {
    __shared__ unsigned As[16 * APAD];
    __shared__ unsigned Bs[16 * BPAD];
    int b = blockIdx.z, m0 = blockIdx.y * 128, n0 = blockIdx.x * 64;
    int tid = threadIdx.x, lane = tid & 31, warp = tid >> 5;
    int g = lane >> 2, tig = lane & 3;
    int wm = warp >> 1, wn = warp & 1;
    const float* xb = x + (size_t)b * DIMC * NTOK;
    float c[2][4][4] = {};
    for (int k0 = 0; k0 < 2048; k0 += 16) {
#pragma unroll
        for (int e = tid; e < 512; e += 256) {
            int kr = e >> 5, c4 = (e & 31) * 4;
            int k = k0 + kr;
            int ii = k >> 2, kh = (k >> 1) & 1, kw = k & 1;
            const float* xp = xb + (size_t)ii * NTOK;
            uint4 t;
            unsigned* tp = (unsigned*)&t;
#pragma unroll
            for (int q = 0; q < 4; q++) {
                int m = m0 + c4 + q;
                float v = 0.f;
                if (m < KTOK) {
                    int ph = m / 28, pw = m - ph * 28;
                    v = xp[(2 * ph + kh) * FSZ + 2 * pw + kw];
                }
                tp[q] = f2tf(v);
            }
            *(uint4*)&As[kr * APAD + c4] = t;
        }
        {
            int nr = tid >> 2, kc4 = (tid & 3) * 4;
            float4 v = *(const float4*)&Wsr[(size_t)(n0 + nr) * 2048 + k0 + kc4];
            Bs[(kc4 + 0) * BPAD + nr] = f2tf(v.x);
            Bs[(kc4 + 1) * BPAD + nr] = f2tf(v.y);
            Bs[(kc4 + 2) * BPAD + nr] = f2tf(v.z);
            Bs[(kc4 + 3) * BPAD + nr] = f2tf(v.w);
        }
        __syncthreads();
        mma_tile16(As, Bs, c, wm, wn, g, tig);
        __syncthreads();
    }
#pragma unroll
    for (int mt = 0; mt < 2; mt++) {
        int r1 = m0 + wm * 32 + mt * 16 + g, r2 = r1 + 8;
#pragma unroll
        for (int nt = 0; nt < 4; nt++) {
            int n = n0 + wn * 32 + nt * 8 + tig * 2;
            float2 bb = *(const float2*)&b_sr[n];
            if (r1 < KTOK)
                *(float2*)&g_xr[((size_t)b * KTOK + r1) * DIMC + n] =
                    make_float2(c[mt][nt][0] + bb.x, c[mt][nt][1] + bb.y);
            if (r2 < KTOK)
                *(float2*)&g_xr[((size_t)b * KTOK + r2) * DIMC + n] =
                    make_float2(c[mt][nt][2] + bb.x, c[mt][nt][3] + bb.y);
        }
    }
}

// ---------------- LayerNorm ----------------
__global__ void ln_kernel(const float* __restrict__ gamma, const float* __restrict__ beta) {
    int row = blockIdx.x;
    float* p = g_xr + (long long)row * DIMC;
    int t = threadIdx.x;
    float v0 = p[t], v1 = p[t + 256];
    float s = v0 + v1, sq = v0 * v0 + v1 * v1;
#pragma unroll
    for (int o = 16; o > 0; o >>= 1) {
        s += __shfl_xor_sync(0xffffffffu, s, o);
        sq += __shfl_xor_sync(0xffffffffu, sq, o);
    }
    __shared__ float rs_[8], rq_[8];
    int lane = t & 31, w = t >> 5;
    if (lane == 0) { rs_[w] = s; rq_[w] = sq; }
    __syncthreads();
    if (t == 0) {
        float S = 0.f, Q = 0.f;
#pragma unroll
        for (int i = 0; i < 8; i++) { S += rs_[i]; Q += rq_[i]; }
        rs_[0] = S; rq_[0] = Q;
    }
    __syncthreads();
    float mu = rs_[0] * (1.f / 512.f);
    float var = rq_[0] * (1.f / 512.f) - mu * mu;
    float inv = rsqrtf(var + LN_EPS);
    p[t] = (v0 - mu) * inv * gamma[t] + beta[t];
    p[t + 256] = (v1 - mu) * inv * gamma[t + 256] + beta[t + 256];
}

// ---------------- GEMM KV (tf32): M=784, N=1024, K=512 ----------------
__global__ __launch_bounds__(256) void gemm_kv(const float* __restrict__ Wkv) {
    __shared__ unsigned As[16 * APAD];
    __shared__ unsigned Bs[16 * BPAD];
    int b = blockIdx.z, m0 = blockIdx.y * 128, n0 = blockIdx.x * 64;
    int tid = threadIdx.x, lane = tid & 31, warp = tid >> 5;
    int g = lane >> 2, tig = lane & 3;
    int wm = warp >> 1, wn = warp & 1;
    const float* A = g_xr + (size_t)b * KTOK * DIMC;
    float c[2][4][4] = {};
    for (int k0 = 0; k0 < DIMC; k0 += 16) {
#pragma unroll
        for (int e = tid; e < 512; e += 256) {
            int mr = e >> 2, kc4 = (e & 3) * 4;
            float4 v = make_float4(0.f, 0.f, 0.f, 0.f);
            if (m0 + mr < KTOK)
                v = *(const float4*)&A[(size_t)(m0 + mr) * DIMC + k0 + kc4];
            As[(kc4 + 0) * APAD + mr] = f2tf(v.x);
            As[(kc4 + 1) * APAD + mr] = f2tf(v.y);
            As[(kc4 + 2) * APAD + mr] = f2tf(v.z);
            As[(kc4 + 3) * APAD + mr] = f2tf(v.w);
        }
        {
            int kr = tid >> 4, c4 = (tid & 15) * 4;
            float4 v = *(const float4*)&Wkv[(size_t)(k0 + kr) * 1024 + n0 + c4];
            *(uint4*)&Bs[kr * BPAD + c4] = tf4(v);
        }
        __syncthreads();
        mma_tile16(As, Bs, c, wm, wn, g, tig);
        __syncthreads();
    }
#pragma unroll
    for (int mt = 0; mt < 2; mt++) {
        int r1 = m0 + wm * 32 + mt * 16 + g, r2 = r1 + 8;
#pragma unroll
        for (int nt = 0; nt < 4; nt++) {
            int n = n0 + wn * 32 + nt * 8 + tig * 2;
            int d = n >> 4, h = (n >> 1) & 7;
            if (r1 < KTOK) {
                size_t dst = (((size_t)b * NHEADS + h) * KTOK + r1) * HD + d;
                g_k[dst] = c[mt][nt][0];
                g_v[dst] = c[mt][nt][1];
            }
            if (r2 < KTOK) {
                size_t dst = (((size_t)b * NHEADS + h) * KTOK + r2) * HD + d;
                g_k[dst] = c[mt][nt][2];
                g_v[dst] = c[mt][nt][3];
            }
        }
    }
}

// ---------------- fused attention (tf32 MMA flash) — R8, unchanged ----------------
__global__ __launch_bounds__(256, 2) void attn_kernel() {
    extern __shared__ __align__(16) unsigned smu[];
    unsigned* Ks = smu;                       // 112*68
    unsigned* Vs = smu + 7616;                // 112*72
    unsigned* Ps = Vs + 8064;                 // 64*132
    float* redm = (float*)(Ps + 8448);        // 128
    float* reds = redm + 128;                 // 128

    int bh = blockIdx.y, row0 = blockIdx.x * 64;
    int tid = threadIdx.x, lane = tid & 31, warp = tid >> 5;
    int g = lane >> 2, tig = lane & 3;
    int wm = warp & 3, wn = warp >> 2;

    const float* qb = g_q + (size_t)bh * NTOK * HD;
    const float* kb = g_k + (size_t)bh * KTOK * HD;
    const float* vb = g_v + (size_t)bh * KTOK * HD;

    int r1 = wm * 16 + g, r2 = r1 + 8;

    unsigned aq[8][4];
    {
        const float* q1 = qb + (size_t)(row0 + r1) * HD;
        const float* q2 = qb + (size_t)(row0 + r2) * HD;
#pragma unroll
        for (int ks = 0; ks < 8; ks++) {
            aq[ks][0] = f2tf(q1[ks * 8 + tig]);
            aq[ks][1] = f2tf(q2[ks * 8 + tig]);
            aq[ks][2] = f2tf(q1[ks * 8 + tig + 4]);
            aq[ks][3] = f2tf(q2[ks * 8 + tig + 4]);
        }
    }
    float run_max1 = -INFINITY, run_max2 = -INFINITY;
    float run_sum1 = 0.f, run_sum2 = 0.f;
    float c_o[4][4] = {};

    for (int t = 0; t < 7; t++) {
        int m0 = t * 112;
        __syncthreads();
        for (int e = tid; e < 112 * 16; e += 256) {
            int mr = e >> 4, d4 = (e & 15) * 4;
            float4 k4 = *(const float4*)&kb[(size_t)(m0 + mr) * HD + d4];
            unsigned* kd = &Ks[mr * 68 + d4];
            kd[0] = f2tf(k4.x); kd[1] = f2tf(k4.y); kd[2] = f2tf(k4.z); kd[3] = f2tf(k4.w);
            float4 v4 = *(const float4*)&vb[(size_t)(m0 + mr) * HD + d4];
            unsigned* vd = &Vs[mr * 72 + d4];
            vd[0] = f2tf(v4.x); vd[1] = f2tf(v4.y); vd[2] = f2tf(v4.z); vd[3] = f2tf(v4.w);
        }
        __syncthreads();

        float cs[7][4] = {};
#pragma unroll
        for (int ks = 0; ks < 8; ks++) {
#pragma unroll
            for (int nt = 0; nt < 7; nt++) {
                int n = wn * 56 + nt * 8 + g;
                unsigned bk[2];
                bk[0] = Ks[n * 68 + ks * 8 + tig];
                bk[1] = Ks[n * 68 + ks * 8 + tig + 4];
                MMA8(cs[nt], aq[ks], bk);
            }
        }
        float p1[14], p2[14];
        float mx1 = -INFINITY, mx2 = -INFINITY;
#pragma unroll
        for (int nt = 0; nt < 7; nt++) {
            int col = m0 + wn * 56 + nt * 8 + tig * 2;
            float2 b1 = *(const float2*)&g_bias[(size_t)(row0 + r1) * KTOK + col];
            float2 b2 = *(const float2*)&g_bias[(size_t)(row0 + r2) * KTOK + col];
            p1[2 * nt]     = cs[nt][0] * ATT_SCALE + b1.x;
            p1[2 * nt + 1] = cs[nt][1] * ATT_SCALE + b1.y;
            p2[2 * nt]     = cs[nt][2] * ATT_SCALE + b2.x;
            p2[2 * nt + 1] = cs[nt][3] * ATT_SCALE + b2.y;
            mx1 = fmaxf(mx1, fmaxf(p1[2 * nt], p1[2 * nt + 1]));
            mx2 = fmaxf(mx2, fmaxf(p2[2 * nt], p2[2 * nt + 1]));
        }
        mx1 = fmaxf(mx1, __shfl_xor_sync(0xffffffffu, mx1, 1));
        mx1 = fmaxf(mx1, __shfl_xor_sync(0xffffffffu, mx1, 2));
        mx2 = fmaxf(mx2, __shfl_xor_sync(0xffffffffu, mx2, 1));
        mx2 = fmaxf(mx2, __shfl_xor_sync(0xffffffffu, mx2, 2));
        if (tig == 0) { redm[wn * 64 + r1] = mx1; redm[wn * 64 + r2] = mx2; }
        __syncthreads();
        float tm1 = fmaxf(redm[r1], redm[64 + r1]);
        float tm2 = fmaxf(redm[r2], redm[64 + r2]);
        float nm1 = fmaxf(run_max1, tm1), nm2 = fmaxf(run_max2, tm2);
        float co1 = __expf(run_max1 - nm1), co2 = __expf(run_max2 - nm2);
        run_max1 = nm1; run_max2 = nm2;
        float s1 = 0.f, s2 = 0.f;
#pragma unroll
        for (int i = 0; i < 14; i++) {
            p1[i] = __expf(p1[i] - nm1); s1 += p1[i];
            p2[i] = __expf(p2[i] - nm2); s2 += p2[i];
        }
        s1 += __shfl_xor_sync(0xffffffffu, s1, 1);
        s1 += __shfl_xor_sync(0xffffffffu, s1, 2);
        s2 += __shfl_xor_sync(0xffffffffu, s2, 1);
        s2 += __shfl_xor_sync(0xffffffffu, s2, 2);
        if (tig == 0) { reds[wn * 64 + r1] = s1; reds[wn * 64 + r2] = s2; }
#pragma unroll
        for (int nt = 0; nt < 7; nt++) {
            int col = wn * 56 + nt * 8 + tig * 2;
            uint2 w1 = make_uint2(f2tf(p1[2 * nt]), f2tf(p1[2 * nt + 1]));
            uint2 w2 = make_uint2(f2tf(p2[2 * nt]), f2tf(p2[2 * nt + 1]));
            *(uint2*)&Ps[r1 * 132 + col] = w1;
            *(uint2*)&Ps[r2 * 132 + col] = w2;
        }
#pragma unroll
        for (int nt = 0; nt < 4; nt++) {
            c_o[nt][0] *= co1; c_o[nt][1] *= co1;
            c_o[nt][2] *= co2; c_o[nt][3] *= co2;
        }
        __syncthreads();
        run_sum1 = run_sum1 * co1 + reds[r1] + reds[64 + r1];
        run_sum2 = run_sum2 * co2 + reds[r2] + reds[64 + r2];
#pragma unroll
        for (int ks = 0; ks < 14; ks++) {
            unsigned ap[4];
            ap[0] = Ps[r1 * 132 + ks * 8 + tig];
            ap[1] = Ps[r2 * 132 + ks * 8 + tig];
            ap[2] = Ps[r1 * 132 + ks * 8 + tig + 4];
            ap[3] = Ps[r2 * 132 + ks * 8 + tig + 4];
#pragma unroll
            for (int nt = 0; nt < 4; nt++) {
                int n = wn * 32 + nt * 8 + g;
                unsigned bv[2];
                bv[0] = Vs[(ks * 8 + tig) * 72 + n];
                bv[1] = Vs[(ks * 8 + tig + 4) * 72 + n];
                MMA8(c_o[nt], ap, bv);
            }
        }
    }
    int b = bh >> 3, h = bh & 7;
    float i1 = 1.f / run_sum1, i2 = 1.f / run_sum2;
#pragma unroll
    for (int nt = 0; nt < 4; nt++) {
        int d = h * HD + wn * 32 + nt * 8 + tig * 2;
        *(float2*)&g_ao[((size_t)b * NTOK + row0 + r1) * DIMC + d] =
            make_float2(c_o[nt][0] * i1, c_o[nt][1] * i1);
        *(float2*)&g_ao[((size_t)b * NTOK + row0 + r2) * DIMC + d] =
            make_float2(c_o[nt][2] * i2, c_o[nt][3] * i2);
    }
}

// ---------------- GEMM out (tf32): [12544,512]@[512,512] + bp, transposed store ----------------
__global__ __launch_bounds__(256) void gemm_out(const float* __restrict__ Wp,
                                                const float* __restrict__ bp,
                                                float* __restrict__ out) {
    __shared__ unsigned As[16 * APAD];
    __shared__ unsigned Bs[16 * BPAD];
    int m0 = blockIdx.y * 128, n0 = blockIdx.x * 64;
    int tid = threadIdx.x, lane = tid & 31, warp = tid >> 5;
    int g = lane >> 2, tig = lane & 3;
    int wm = warp >> 1, wn = warp & 1;
    float c[2][4][4] = {};
    for (int k0 = 0; k0 < DIMC; k0 += 16) {
#pragma unroll
        for (int e = tid; e < 512; e += 256) {
            int mr = e >> 2, kc4 = (e & 3) * 4;
            float4 v = *(const float4*)&g_ao[(size_t)(m0 + mr) * DIMC + k0 + kc4];
            As[(kc4 + 0) * APAD + mr] = f2tf(v.x);
            As[(kc4 + 1) * APAD + mr] = f2tf(v.y);
            As[(kc4 + 2) * APAD + mr] = f2tf(v.z);
            As[(kc4 + 3) * APAD + mr] = f2tf(v.w);
        }
        {
            int kr = tid >> 4, c4 = (tid & 15) * 4;
            float4 v = *(const float4*)&Wp[(size_t)(k0 + kr) * DIMC + n0 + c4];
            *(uint4*)&Bs[kr * BPAD + c4] = tf4(v);
        }
        __syncthreads();
        mma_tile16(As, Bs, c, wm, wn, g, tig);
        __syncthreads();
    }
#pragma unroll
    for (int mt = 0; mt < 2; mt++) {
        int r1 = m0 + wm * 32 + mt * 16 + g, r2 = r1 + 8;
        int b1 = r1 / NTOK, n1 = r1 - b1 * NTOK;
        int b2 = r2 / NTOK, n2 = r2 - b2 * NTOK;
#pragma unroll
        for (int nt = 0; nt < 4; nt++) {
            int cc = n0 + wn * 32 + nt * 8 + tig * 2;
            float bb0 = bp[cc], bb1 = bp[cc + 1];
            out[((size_t)b1 * DIMC + cc) * NTOK + n1] = c[mt][nt][0] + bb0;
            out[((size_t)b1 * DIMC + cc + 1) * NTOK + n1] = c[mt][nt][1] + bb1;
            out[((size_t)b2 * DIMC + cc) * NTOK + n2] = c[mt][nt][2] + bb0;
            out[((size_t)b2 * DIMC + cc + 1) * NTOK + n2] = c[mt][nt][3] + bb1;
        }
    }
}

// ---------------- launch (with fork/join concurrency) ----------------
extern "C" void kernel_launch(void* const* d_in, const int* in_sizes, int n_in,
                              void* d_out, int out_size) {
    const float* x     = (const float*)d_in[0];
    const float* Wq    = (const float*)d_in[1];
    const float* Wkv   = (const float*)d_in[2];
    const float* Wsr   = (const float*)d_in[3];
    const float* b_sr  = (const float*)d_in[4];
    const float* gamma = (const float*)d_in[5];
    const float* beta  = (const float*)d_in[6];
    const float* Wp    = (const float*)d_in[7];
    const float* bp    = (const float*)d_in[8];
    const float* pos   = (const float*)d_in[9];
    const int*   rel   = (const int*)d_in[10];
    float* out = (float*)d_out;

    const int ATT_SMEM = (7616 + 8064 + 8448 + 256) * 4;  // 97,536 B
    cudaFuncSetAttribute(attn_kernel, cudaFuncAttributeMaxDynamicSharedMemorySize, ATT_SMEM);

    // one-time host-side stream/event setup (no device memory involved)
    static cudaStream_t s2 = nullptr;
    static cudaEvent_t evFork = nullptr, evJoin = nullptr;
    if (s2 == nullptr) {
        cudaStreamCreateWithFlags(&s2, cudaStreamNonBlocking);
        cudaEventCreateWithFlags(&evFork, cudaEventDisableTiming);
        cudaEventCreateWithFlags(&evJoin, cudaEventDisableTiming);
    }

    // fork: gemm_q is independent of the conv->ln->kv chain
    cudaEventRecord(evFork, 0);
    cudaStreamWaitEvent(s2, evFork, 0);
    gemm_q<<<dim3(8, 25, BATCH), 256, 0, s2>>>(x, Wq);
    cudaEventRecord(evJoin, s2);

    // main stream: bias + conv -> ln -> kv (runs concurrently with gemm_q)
    bias_kernel<<<(NTOK * KTOK / 2 + 255) / 256, 256>>>(pos, rel);
    gemm_conv<<<dim3(8, 7, BATCH), 256>>>(x, Wsr, b_sr);
    ln_kernel<<<BATCH * KTOK, 256>>>(gamma, beta);
    gemm_kv<<<dim3(16, 7, BATCH), 256>>>(Wkv);

    // join, then attention + output projection
    cudaStreamWaitEvent(0, evJoin, 0);
    attn_kernel<<<dim3(49, 32), 256, ATT_SMEM>>>();
    gemm_out<<<dim3(8, 98, 1), 256>>>(Wp, bp, out);
}

// round 16
// speedup vs baseline: 1.4733x; 1.4733x over previous
#include <cuda_runtime.h>
#include <math.h>

#define DIMC 512
#define NHEADS 8
#define HD 64
#define FSZ 56
#define NTOK 3136
#define KTOK 784
#define BATCH 4
#define ATT_SCALE 0.125f
#define LN_EPS 1e-5f
#define POSW 111

// ---------------- scratch ----------------
__device__ float g_bias[NTOK * KTOK];
__device__ float g_q[BATCH * NHEADS * NTOK * HD];
__device__ float g_xr[BATCH * KTOK * DIMC];
__device__ float g_k[BATCH * NHEADS * KTOK * HD];
__device__ float g_v[BATCH * NHEADS * KTOK * HD];
__device__ float g_ao[BATCH * NTOK * DIMC];

// ---------------- tf32 helpers ----------------
__device__ __forceinline__ unsigned f2tf(float f) {
    unsigned u; asm("cvt.rna.tf32.f32 %0, %1;" : "=r"(u) : "f"(f)); return u;
}
__device__ __forceinline__ uint4 tf4(float4 v) {
    uint4 t; t.x = f2tf(v.x); t.y = f2tf(v.y); t.z = f2tf(v.z); t.w = f2tf(v.w); return t;
}
#define MMA8(C, A, B)                                                          \
    asm volatile(                                                              \
        "mma.sync.aligned.m16n8k8.row.col.f32.tf32.tf32.f32 "                  \
        "{%0,%1,%2,%3},{%4,%5,%6,%7},{%8,%9},{%0,%1,%2,%3};"                   \
        : "+f"((C)[0]), "+f"((C)[1]), "+f"((C)[2]), "+f"((C)[3])               \
        : "r"((A)[0]), "r"((A)[1]), "r"((A)[2]), "r"((A)[3]),                  \
          "r"((B)[0]), "r"((B)[1]))

#define APAD 136
#define BPAD 72

// Fragment compute for one 16-k tile: As[16][APAD] (k,m), Bs[16][BPAD] (k,n).
__device__ __forceinline__ void mma_tile16(const unsigned* __restrict__ As,
                                           const unsigned* __restrict__ Bs,
                                           float c[2][4][4], int wm, int wn,
                                           int g, int tig) {
#pragma unroll
    for (int kk = 0; kk < 16; kk += 8) {
        unsigned a[2][4], bf[4][2];
#pragma unroll
        for (int mt = 0; mt < 2; mt++) {
            int mr = wm * 32 + mt * 16 + g;
            a[mt][0] = As[(kk + tig) * APAD + mr];
            a[mt][1] = As[(kk + tig) * APAD + mr + 8];
            a[mt][2] = As[(kk + tig + 4) * APAD + mr];
            a[mt][3] = As[(kk + tig + 4) * APAD + mr + 8];
        }
#pragma unroll
        for (int nt = 0; nt < 4; nt++) {
            int nc = wn * 32 + nt * 8 + g;
            bf[nt][0] = Bs[(kk + tig) * BPAD + nc];
            bf[nt][1] = Bs[(kk + tig + 4) * BPAD + nc];
        }
#pragma unroll
        for (int mt = 0; mt < 2; mt++)
#pragma unroll
            for (int nt = 0; nt < 4; nt++) MMA8(c[mt][nt], a[mt], bf[nt]);
    }
}

// ---------------- bias precompute (2 elems/thread) ----------------
__global__ void bias_kernel(const float* __restrict__ pos, const int* __restrict__ rel) {
    int i = blockIdx.x * 256 + threadIdx.x;
    if (i >= NTOK * KTOK / 2) return;
    int e = 2 * i;
    int n = e / KTOK, m = e % KTOK;
    int4 r = *(const int4*)&rel[((long long)n * NTOK + m) * 2];
    float2 o;
    o.x = pos[r.x * POSW + r.y];
    o.y = pos[r.z * POSW + r.w];
    *(float2*)&g_bias[e] = o;
}

// ---------------- GEMM Q (tf32): A[m][k]=x[b][k][m], B=Wq. M=3136,N=512,K=512 ----------------
__global__ __launch_bounds__(256) void gemm_q(const float* __restrict__ x,
                                              const float* __restrict__ Wq) {
    __shared__ unsigned As[16 * APAD];
    __shared__ unsigned Bs[16 * BPAD];
    int b = blockIdx.z, m0 = blockIdx.y * 128, n0 = blockIdx.x * 64;
    int tid = threadIdx.x, lane = tid & 31, warp = tid >> 5;
    int g = lane >> 2, tig = lane & 3;
    int wm = warp >> 1, wn = warp & 1;
    const float* xb = x + (size_t)b * DIMC * NTOK;
    float c[2][4][4] = {};
    for (int k0 = 0; k0 < DIMC; k0 += 16) {
#pragma unroll
        for (int e = tid; e < 512; e += 256) {
            int kr = e >> 5, c4 = (e & 31) * 4;
            float4 v = make_float4(0.f, 0.f, 0.f, 0.f);
            if (m0 + c4 < NTOK)
                v = *(const float4*)&xb[(size_t)(k0 + kr) * NTOK + m0 + c4];
            *(uint4*)&As[kr * APAD + c4] = tf4(v);
        }
        {
            int kr = tid >> 4, c4 = (tid & 15) * 4;
            float4 v = *(const float4*)&Wq[(size_t)(k0 + kr) * DIMC + n0 + c4];
            *(uint4*)&Bs[kr * BPAD + c4] = tf4(v);
        }
        __syncthreads();
        mma_tile16(As, Bs, c, wm, wn, g, tig);
        __syncthreads();
    }
#pragma unroll
    for (int mt = 0; mt < 2; mt++) {
        int r1 = m0 + wm * 32 + mt * 16 + g, r2 = r1 + 8;
#pragma unroll
        for (int nt = 0; nt < 4; nt++) {
            int n = n0 + wn * 32 + nt * 8 + tig * 2;
            int h = n >> 6, d = n & 63;
            if (r1 < NTOK)
                *(float2*)&g_q[(((size_t)b * NHEADS + h) * NTOK + r1) * HD + d] =
                    make_float2(c[mt][nt][0], c[mt][nt][1]);
            if (r2 < NTOK)
                *(float2*)&g_q[(((size_t)b * NHEADS + h) * NTOK + r2) * HD + d] =
                    make_float2(c[mt][nt][2], c[mt][nt][3]);
        }
    }
}

// ---------------- GEMM conv (tf32): im2col, M=784, N=512, K=2048 ----------------
__global__ __launch_bounds__(256) void gemm_conv(const float* __restrict__ x,
                                                 const float* __restrict__ Wsr,
                                                 const float* __restrict__ b_sr) {
    __shared__ unsigned As[16 * APAD];
    __shared__ unsigned Bs[16 * BPAD];
    int b = blockIdx.z, m0 = blockIdx.y * 128, n0 = blockIdx.x * 64;
    int tid = threadIdx.x, lane = tid & 31, warp = tid >> 5;
    int g = lane >> 2, tig = lane & 3;
    int wm = warp >> 1, wn = warp & 1;
    const float* xb = x + (size_t)b * DIMC * NTOK;
    float c[2][4][4] = {};
    for (int k0 = 0; k0 < 2048; k0 += 16) {
#pragma unroll
        for (int e = tid; e < 512; e += 256) {
            int kr = e >> 5, c4 = (e & 31) * 4;
            int k = k0 + kr;
            int ii = k >> 2, kh = (k >> 1) & 1, kw = k & 1;
            const float* xp = xb + (size_t)ii * NTOK;
            uint4 t;
            unsigned* tp = (unsigned*)&t;
#pragma unroll
            for (int q = 0; q < 4; q++) {
                int m = m0 + c4 + q;
                float v = 0.f;
                if (m < KTOK) {
                    int ph = m / 28, pw = m - ph * 28;
                    v = xp[(2 * ph + kh) * FSZ + 2 * pw + kw];
                }
                tp[q] = f2tf(v);
            }
            *(uint4*)&As[kr * APAD + c4] = t;
        }
        {
            int nr = tid >> 2, kc4 = (tid & 3) * 4;
            float4 v = *(const float4*)&Wsr[(size_t)(n0 + nr) * 2048 + k0 + kc4];
            Bs[(kc4 + 0) * BPAD + nr] = f2tf(v.x);
            Bs[(kc4 + 1) * BPAD + nr] = f2tf(v.y);
            Bs[(kc4 + 2) * BPAD + nr] = f2tf(v.z);
            Bs[(kc4 + 3) * BPAD + nr] = f2tf(v.w);
        }
        __syncthreads();
        mma_tile16(As, Bs, c, wm, wn, g, tig);
        __syncthreads();
    }
#pragma unroll
    for (int mt = 0; mt < 2; mt++) {
        int r1 = m0 + wm * 32 + mt * 16 + g, r2 = r1 + 8;
#pragma unroll
        for (int nt = 0; nt < 4; nt++) {
            int n = n0 + wn * 32 + nt * 8 + tig * 2;
            float2 bb = *(const float2*)&b_sr[n];
            if (r1 < KTOK)
                *(float2*)&g_xr[((size_t)b * KTOK + r1) * DIMC + n] =
                    make_float2(c[mt][nt][0] + bb.x, c[mt][nt][1] + bb.y);
            if (r2 < KTOK)
                *(float2*)&g_xr[((size_t)b * KTOK + r2) * DIMC + n] =
                    make_float2(c[mt][nt][2] + bb.x, c[mt][nt][3] + bb.y);
        }
    }
}

// ---------------- LayerNorm ----------------
__global__ void ln_kernel(const float* __restrict__ gamma, const float* __restrict__ beta) {
    int row = blockIdx.x;
    float* p = g_xr + (long long)row * DIMC;
    int t = threadIdx.x;
    float v0 = p[t], v1 = p[t + 256];
    float s = v0 + v1, sq = v0 * v0 + v1 * v1;
#pragma unroll
    for (int o = 16; o > 0; o >>= 1) {
        s += __shfl_xor_sync(0xffffffffu, s, o);
        sq += __shfl_xor_sync(0xffffffffu, sq, o);
    }
    __shared__ float rs_[8], rq_[8];
    int lane = t & 31, w = t >> 5;
    if (lane == 0) { rs_[w] = s; rq_[w] = sq; }
    __syncthreads();
    if (t == 0) {
        float S = 0.f, Q = 0.f;
#pragma unroll
        for (int i = 0; i < 8; i++) { S += rs_[i]; Q += rq_[i]; }
        rs_[0] = S; rq_[0] = Q;
    }
    __syncthreads();
    float mu = rs_[0] * (1.f / 512.f);
    float var = rq_[0] * (1.f / 512.f) - mu * mu;
    float inv = rsqrtf(var + LN_EPS);
    p[t] = (v0 - mu) * inv * gamma[t] + beta[t];
    p[t + 256] = (v1 - mu) * inv * gamma[t + 256] + beta[t + 256];
}

// ---------------- GEMM KV (tf32): M=784, N=1024, K=512 ----------------
__global__ __launch_bounds__(256) void gemm_kv(const float* __restrict__ Wkv) {
    __shared__ unsigned As[16 * APAD];
    __shared__ unsigned Bs[16 * BPAD];
    int b = blockIdx.z, m0 = blockIdx.y * 128, n0 = blockIdx.x * 64;
    int tid = threadIdx.x, lane = tid & 31, warp = tid >> 5;
    int g = lane >> 2, tig = lane & 3;
    int wm = warp >> 1, wn = warp & 1;
    const float* A = g_xr + (size_t)b * KTOK * DIMC;
    float c[2][4][4] = {};
    for (int k0 = 0; k0 < DIMC; k0 += 16) {
#pragma unroll
        for (int e = tid; e < 512; e += 256) {
            int mr = e >> 2, kc4 = (e & 3) * 4;
            float4 v = make_float4(0.f, 0.f, 0.f, 0.f);
            if (m0 + mr < KTOK)
                v = *(const float4*)&A[(size_t)(m0 + mr) * DIMC + k0 + kc4];
            As[(kc4 + 0) * APAD + mr] = f2tf(v.x);
            As[(kc4 + 1) * APAD + mr] = f2tf(v.y);
            As[(kc4 + 2) * APAD + mr] = f2tf(v.z);
            As[(kc4 + 3) * APAD + mr] = f2tf(v.w);
        }
        {
            int kr = tid >> 4, c4 = (tid & 15) * 4;
            float4 v = *(const float4*)&Wkv[(size_t)(k0 + kr) * 1024 + n0 + c4];
            *(uint4*)&Bs[kr * BPAD + c4] = tf4(v);
        }
        __syncthreads();
        mma_tile16(As, Bs, c, wm, wn, g, tig);
        __syncthreads();
    }
#pragma unroll
    for (int mt = 0; mt < 2; mt++) {
        int r1 = m0 + wm * 32 + mt * 16 + g, r2 = r1 + 8;
#pragma unroll
        for (int nt = 0; nt < 4; nt++) {
            int n = n0 + wn * 32 + nt * 8 + tig * 2;
            int d = n >> 4, h = (n >> 1) & 7;
            if (r1 < KTOK) {
                size_t dst = (((size_t)b * NHEADS + h) * KTOK + r1) * HD + d;
                g_k[dst] = c[mt][nt][0];
                g_v[dst] = c[mt][nt][1];
            }
            if (r2 < KTOK) {
                size_t dst = (((size_t)b * NHEADS + h) * KTOK + r2) * HD + d;
                g_k[dst] = c[mt][nt][2];
                g_v[dst] = c[mt][nt][3];
            }
        }
    }
}

// ---------------- fused attention (tf32 MMA flash) ----------------
__global__ __launch_bounds__(256, 2) void attn_kernel() {
    extern __shared__ __align__(16) unsigned smu[];
    unsigned* Ks = smu;                       // 112*68
    unsigned* Vs = smu + 7616;                // 112*72
    unsigned* Ps = Vs + 8064;                 // 64*132
    float* redm = (float*)(Ps + 8448);        // 128
    float* reds = redm + 128;                 // 128

    int bh = blockIdx.y, row0 = blockIdx.x * 64;
    int tid = threadIdx.x, lane = tid & 31, warp = tid >> 5;
    int g = lane >> 2, tig = lane & 3;
    int wm = warp & 3, wn = warp >> 2;

    const float* qb = g_q + (size_t)bh * NTOK * HD;
    const float* kb = g_k + (size_t)bh * KTOK * HD;
    const float* vb = g_v + (size_t)bh * KTOK * HD;

    int r1 = wm * 16 + g, r2 = r1 + 8;

    unsigned aq[8][4];
    {
        const float* q1 = qb + (size_t)(row0 + r1) * HD;
        const float* q2 = qb + (size_t)(row0 + r2) * HD;
#pragma unroll
        for (int ks = 0; ks < 8; ks++) {
            aq[ks][0] = f2tf(q1[ks * 8 + tig]);
            aq[ks][1] = f2tf(q2[ks * 8 + tig]);
            aq[ks][2] = f2tf(q1[ks * 8 + tig + 4]);
            aq[ks][3] = f2tf(q2[ks * 8 + tig + 4]);
        }
    }
    float run_max1 = -INFINITY, run_max2 = -INFINITY;
    float run_sum1 = 0.f, run_sum2 = 0.f;
    float c_o[4][4] = {};

    for (int t = 0; t < 7; t++) {
        int m0 = t * 112;
        __syncthreads();
        for (int e = tid; e < 112 * 16; e += 256) {
            int mr = e >> 4, d4 = (e & 15) * 4;
            float4 k4 = *(const float4*)&kb[(size_t)(m0 + mr) * HD + d4];
            unsigned* kd = &Ks[mr * 68 + d4];
            kd[0] = f2tf(k4.x); kd[1] = f2tf(k4.y); kd[2] = f2tf(k4.z); kd[3] = f2tf(k4.w);
            float4 v4 = *(const float4*)&vb[(size_t)(m0 + mr) * HD + d4];
            unsigned* vd = &Vs[mr * 72 + d4];
            vd[0] = f2tf(v4.x); vd[1] = f2tf(v4.y); vd[2] = f2tf(v4.z); vd[3] = f2tf(v4.w);
        }
        __syncthreads();

        float cs[7][4] = {};
#pragma unroll
        for (int ks = 0; ks < 8; ks++) {
#pragma unroll
            for (int nt = 0; nt < 7; nt++) {
                int n = wn * 56 + nt * 8 + g;
                unsigned bk[2];
                bk[0] = Ks[n * 68 + ks * 8 + tig];
                bk[1] = Ks[n * 68 + ks * 8 + tig + 4];
                MMA8(cs[nt], aq[ks], bk);
            }
        }
        float p1[14], p2[14];
        float mx1 = -INFINITY, mx2 = -INFINITY;
#pragma unroll
        for (int nt = 0; nt < 7; nt++) {
            int col = m0 + wn * 56 + nt * 8 + tig * 2;
            float2 b1 = *(const float2*)&g_bias[(size_t)(row0 + r1) * KTOK + col];
            float2 b2 = *(const float2*)&g_bias[(size_t)(row0 + r2) * KTOK + col];
            p1[2 * nt]     = cs[nt][0] * ATT_SCALE + b1.x;
            p1[2 * nt + 1] = cs[nt][1] * ATT_SCALE + b1.y;
            p2[2 * nt]     = cs[nt][2] * ATT_SCALE + b2.x;
            p2[2 * nt + 1] = cs[nt][3] * ATT_SCALE + b2.y;
            mx1 = fmaxf(mx1, fmaxf(p1[2 * nt], p1[2 * nt + 1]));
            mx2 = fmaxf(mx2, fmaxf(p2[2 * nt], p2[2 * nt + 1]));
        }
        mx1 = fmaxf(mx1, __shfl_xor_sync(0xffffffffu, mx1, 1));
        mx1 = fmaxf(mx1, __shfl_xor_sync(0xffffffffu, mx1, 2));
        mx2 = fmaxf(mx2, __shfl_xor_sync(0xffffffffu, mx2, 1));
        mx2 = fmaxf(mx2, __shfl_xor_sync(0xffffffffu, mx2, 2));
        if (tig == 0) { redm[wn * 64 + r1] = mx1; redm[wn * 64 + r2] = mx2; }
        __syncthreads();
        float tm1 = fmaxf(redm[r1], redm[64 + r1]);
        float tm2 = fmaxf(redm[r2], redm[64 + r2]);
        float nm1 = fmaxf(run_max1, tm1), nm2 = fmaxf(run_max2, tm2);
        float co1 = __expf(run_max1 - nm1), co2 = __expf(run_max2 - nm2);
        run_max1 = nm1; run_max2 = nm2;
        float s1 = 0.f, s2 = 0.f;
#pragma unroll
        for (int i = 0; i < 14; i++) {
            p1[i] = __expf(p1[i] - nm1); s1 += p1[i];
            p2[i] = __expf(p2[i] - nm2); s2 += p2[i];
        }
        s1 += __shfl_xor_sync(0xffffffffu, s1, 1);
        s1 += __shfl_xor_sync(0xffffffffu, s1, 2);
        s2 += __shfl_xor_sync(0xffffffffu, s2, 1);
        s2 += __shfl_xor_sync(0xffffffffu, s2, 2);
        if (tig == 0) { reds[wn * 64 + r1] = s1; reds[wn * 64 + r2] = s2; }
#pragma unroll
        for (int nt = 0; nt < 7; nt++) {
            int col = wn * 56 + nt * 8 + tig * 2;
            uint2 w1 = make_uint2(f2tf(p1[2 * nt]), f2tf(p1[2 * nt + 1]));
            uint2 w2 = make_uint2(f2tf(p2[2 * nt]), f2tf(p2[2 * nt + 1]));
            *(uint2*)&Ps[r1 * 132 + col] = w1;
            *(uint2*)&Ps[r2 * 132 + col] = w2;
        }
#pragma unroll
        for (int nt = 0; nt < 4; nt++) {
            c_o[nt][0] *= co1; c_o[nt][1] *= co1;
            c_o[nt][2] *= co2; c_o[nt][3] *= co2;
        }
        __syncthreads();
        run_sum1 = run_sum1 * co1 + reds[r1] + reds[64 + r1];
        run_sum2 = run_sum2 * co2 + reds[r2] + reds[64 + r2];
#pragma unroll
        for (int ks = 0; ks < 14; ks++) {
            unsigned ap[4];
            ap[0] = Ps[r1 * 132 + ks * 8 + tig];
            ap[1] = Ps[r2 * 132 + ks * 8 + tig];
            ap[2] = Ps[r1 * 132 + ks * 8 + tig + 4];
            ap[3] = Ps[r2 * 132 + ks * 8 + tig + 4];
#pragma unroll
            for (int nt = 0; nt < 4; nt++) {
                int n = wn * 32 + nt * 8 + g;
                unsigned bv[2];
                bv[0] = Vs[(ks * 8 + tig) * 72 + n];
                bv[1] = Vs[(ks * 8 + tig + 4) * 72 + n];
                MMA8(c_o[nt], ap, bv);
            }
        }
    }
    int b = bh >> 3, h = bh & 7;
    float i1 = 1.f / run_sum1, i2 = 1.f / run_sum2;
#pragma unroll
    for (int nt = 0; nt < 4; nt++) {
        int d = h * HD + wn * 32 + nt * 8 + tig * 2;
        *(float2*)&g_ao[((size_t)b * NTOK + row0 + r1) * DIMC + d] =
            make_float2(c_o[nt][0] * i1, c_o[nt][1] * i1);
        *(float2*)&g_ao[((size_t)b * NTOK + row0 + r2) * DIMC + d] =
            make_float2(c_o[nt][2] * i2, c_o[nt][3] * i2);
    }
}

// ---------------- GEMM out (tf32): [12544,512]@[512,512] + bp, transposed store ----------------
__global__ __launch_bounds__(256) void gemm_out(const float* __restrict__ Wp,
                                                const float* __restrict__ bp,
                                                float* __restrict__ out) {
    __shared__ unsigned As[16 * APAD];
    __shared__ unsigned Bs[16 * BPAD];
    int m0 = blockIdx.y * 128, n0 = blockIdx.x * 64;
    int tid = threadIdx.x, lane = tid & 31, warp = tid >> 5;
    int g = lane >> 2, tig = lane & 3;
    int wm = warp >> 1, wn = warp & 1;
    float c[2][4][4] = {};
    for (int k0 = 0; k0 < DIMC; k0 += 16) {
#pragma unroll
        for (int e = tid; e < 512; e += 256) {
            int mr = e >> 2, kc4 = (e & 3) * 4;
            float4 v = *(const float4*)&g_ao[(size_t)(m0 + mr) * DIMC + k0 + kc4];
            As[(kc4 + 0) * APAD + mr] = f2tf(v.x);
            As[(kc4 + 1) * APAD + mr] = f2tf(v.y);
            As[(kc4 + 2) * APAD + mr] = f2tf(v.z);
            As[(kc4 + 3) * APAD + mr] = f2tf(v.w);
        }
        {
            int kr = tid >> 4, c4 = (tid & 15) * 4;
            float4 v = *(const float4*)&Wp[(size_t)(k0 + kr) * DIMC + n0 + c4];
            *(uint4*)&Bs[kr * BPAD + c4] = tf4(v);
        }
        __syncthreads();
        mma_tile16(As, Bs, c, wm, wn, g, tig);
        __syncthreads();
    }
#pragma unroll
    for (int mt = 0; mt < 2; mt++) {
        int r1 = m0 + wm * 32 + mt * 16 + g, r2 = r1 + 8;
        int b1 = r1 / NTOK, n1 = r1 - b1 * NTOK;
        int b2 = r2 / NTOK, n2 = r2 - b2 * NTOK;
#pragma unroll
        for (int nt = 0; nt < 4; nt++) {
            int cc = n0 + wn * 32 + nt * 8 + tig * 2;
            float bb0 = bp[cc], bb1 = bp[cc + 1];
            out[((size_t)b1 * DIMC + cc) * NTOK + n1] = c[mt][nt][0] + bb0;
            out[((size_t)b1 * DIMC + cc + 1) * NTOK + n1] = c[mt][nt][1] + bb1;
            out[((size_t)b2 * DIMC + cc) * NTOK + n2] = c[mt][nt][2] + bb0;
            out[((size_t)b2 * DIMC + cc + 1) * NTOK + n2] = c[mt][nt][3] + bb1;
        }
    }
}

// ---------------- launch (single stream, R8 schedule) ----------------
extern "C" void kernel_launch(void* const* d_in, const int* in_sizes, int n_in,
                              void* d_out, int out_size) {
    const float* x     = (const float*)d_in[0];
    const float* Wq    = (const float*)d_in[1];
    const float* Wkv   = (const float*)d_in[2];
    const float* Wsr   = (const float*)d_in[3];
    const float* b_sr  = (const float*)d_in[4];
    const float* gamma = (const float*)d_in[5];
    const float* beta  = (const float*)d_in[6];
    const float* Wp    = (const float*)d_in[7];
    const float* bp    = (const float*)d_in[8];
    const float* pos   = (const float*)d_in[9];
    const int*   rel   = (const int*)d_in[10];
    float* out = (float*)d_out;

    const int ATT_SMEM = (7616 + 8064 + 8448 + 256) * 4;  // 97,536 B
    cudaFuncSetAttribute(attn_kernel, cudaFuncAttributeMaxDynamicSharedMemorySize, ATT_SMEM);

    bias_kernel<<<(NTOK * KTOK / 2 + 255) / 256, 256>>>(pos, rel);
    gemm_q<<<dim3(8, 25, BATCH), 256>>>(x, Wq);
    gemm_conv<<<dim3(8, 7, BATCH), 256>>>(x, Wsr, b_sr);
    ln_kernel<<<BATCH * KTOK, 256>>>(gamma, beta);
    gemm_kv<<<dim3(16, 7, BATCH), 256>>>(Wkv);
    attn_kernel<<<dim3(49, 32), 256, ATT_SMEM>>>();
    gemm_out<<<dim3(8, 98, 1), 256>>>(Wp, bp, out);
}